// round 2
// baseline (speedup 1.0000x reference)
#include <cuda_runtime.h>
#include <cuda_bf16.h>
#include <cstdint>

// Problem constants
#define T_STEPS 1000
#define NB 64          // batch
#define HS 256         // hidden size
#define NCTA 128       // persistent grid
#define NTHR 384       // 6 pairs x 64 batch

// ---------------- device scratch (allocation-free) ----------------
__device__ float g_X[64000 * 256];                    // gathered embeddings [r=(t*64+b)][k]
__device__ float g_P[(size_t)64000 * 3072];           // precomputed x@Wx+b, layout [t][col][b]
__device__ float g_h[2][3 * 128 * 64 * 2];            // h ping-pong, [buf][(l*128+k2)*64+b][2]
__device__ unsigned g_cnt;                            // grid barrier count
__device__ unsigned g_gen;                            // grid barrier generation (monotonic)

// ---------------- gather: X[r][k] = emb[ids[b][t]][k] ----------------
__global__ void gather_kernel(const int* __restrict__ ids, const float* __restrict__ emb) {
    int r = blockIdx.x;           // r = t*64 + b
    int t = r >> 6, b = r & 63;
    int id = ids[b * 1000 + t];
    const float4* src = (const float4*)(emb + (size_t)id * 256);
    float4* dst = (float4*)(g_X + (size_t)r * 256);
    dst[threadIdx.x] = src[threadIdx.x];   // 64 threads * float4 = 256 floats
}

// ---------------- GEMM: P = X @ Wcat + bias (transposed store) ----------------
// M=64000, N=3072, K=256. 128x128 tile, 256 threads, 8x8 micro, k-chunk 8.
__global__ void __launch_bounds__(256) gemm_kernel(
    const float* __restrict__ W0x, const float* __restrict__ W1x, const float* __restrict__ W2x,
    const float* __restrict__ b0,  const float* __restrict__ b1,  const float* __restrict__ b2)
{
    __shared__ __align__(16) float As[8][128];
    __shared__ __align__(16) float Bs[8][128];

    const int tid = threadIdx.x;
    const int rbase = blockIdx.x * 128;
    const int cbase = blockIdx.y * 128;          // 3072/128 = 24 tiles, each within one layer
    const int l = cbase / 1024;
    const int cc0 = cbase & 1023;

    const float* W    = (l == 0) ? W0x : ((l == 1) ? W1x : W2x);
    const float* bias = (l == 0) ? b0  : ((l == 1) ? b1  : b2);

    // A-load mapping: 128 rows x 8 k = 1024 elts = 4/thread (one float4 along k)
    const int am = tid & 127;
    const int aj = tid >> 7;                     // 0..1 -> k quad
    // B-load mapping: 8 k x 128 cols = 4/thread (one float4 along c)
    const int bc = (tid & 31) << 2;
    const int bk = tid >> 5;                     // 0..7

    const int tx = tid & 15, ty = tid >> 4;      // 16x16 thread grid, 8x8 micro

    float acc[8][8];
#pragma unroll
    for (int i = 0; i < 8; i++)
#pragma unroll
        for (int j = 0; j < 8; j++) acc[i][j] = 0.0f;

    for (int k0 = 0; k0 < 256; k0 += 8) {
        float4 av = *(const float4*)(g_X + (size_t)(rbase + am) * 256 + k0 + aj * 4);
        float4 bv = *(const float4*)(W + (size_t)(k0 + bk) * 1024 + cc0 + bc);
        __syncthreads();
        As[aj * 4 + 0][am] = av.x;
        As[aj * 4 + 1][am] = av.y;
        As[aj * 4 + 2][am] = av.z;
        As[aj * 4 + 3][am] = av.w;
        *(float4*)&Bs[bk][bc] = bv;
        __syncthreads();
#pragma unroll
        for (int k = 0; k < 8; k++) {
            float4 a0 = *(const float4*)&As[k][ty * 8];
            float4 a1 = *(const float4*)&As[k][ty * 8 + 4];
            float4 c0 = *(const float4*)&Bs[k][tx * 8];
            float4 c1 = *(const float4*)&Bs[k][tx * 8 + 4];
            float aa[8] = {a0.x, a0.y, a0.z, a0.w, a1.x, a1.y, a1.z, a1.w};
            float cc[8] = {c0.x, c0.y, c0.z, c0.w, c1.x, c1.y, c1.z, c1.w};
#pragma unroll
            for (int i = 0; i < 8; i++)
#pragma unroll
                for (int j = 0; j < 8; j++) acc[i][j] += aa[i] * cc[j];
        }
    }

    // Epilogue: P[(t*3072 + c)*64 + b] = acc + bias[c%1024]
    int tt = (rbase >> 6) + ((ty >= 8) ? 1 : 0);
    int bb0 = (ty * 8) & 63;
#pragma unroll
    for (int j = 0; j < 8; j++) {
        int ccol = cbase + tx * 8 + j;
        float bi = bias[ccol & 1023];
        float4 v0 = make_float4(acc[0][j] + bi, acc[1][j] + bi, acc[2][j] + bi, acc[3][j] + bi);
        float4 v1 = make_float4(acc[4][j] + bi, acc[5][j] + bi, acc[6][j] + bi, acc[7][j] + bi);
        size_t o = ((size_t)tt * 3072 + ccol) * 64 + bb0;
        *(float4*)(g_P + o) = v0;
        *(float4*)(g_P + o + 4) = v1;
    }
}

// ---------------- recurrent persistent kernel ----------------
__device__ __forceinline__ float sigf(float x) { return 1.0f / (1.0f + __expf(-x)); }

__device__ __forceinline__ void gridbar(unsigned target) {
    __syncthreads();
    if (threadIdx.x == 0) {
        __threadfence();
        unsigned old = atomicAdd(&g_cnt, 1u);
        if (old == NCTA - 1) {
            g_cnt = 0u;
            __threadfence();
            atomicExch(&g_gen, target);
        } else {
            while (*((volatile unsigned*)&g_gen) != target) { }
        }
        __threadfence();   // acquire: invalidates L1 so new h is visible
    }
    __syncthreads();
}

__global__ void __launch_bounds__(NTHR) lstm_kernel(
    const float* __restrict__ W0h, const float* __restrict__ W1h, const float* __restrict__ W2h,
    const float* __restrict__ W1x, const float* __restrict__ W2x,
    float* __restrict__ out)
{
    __shared__ float4 wh4[6][256];    // 24 KB: Wh columns (4 gates) per pair
    __shared__ float4 wx4[4][256];    // 16 KB: Wx bottom-half columns for l>=1 pairs
    __shared__ float4 psum[6][64];    //  6 KB: phase B/C partial exchange

    const int tid = threadIdx.x;
    const int cta = blockIdx.x;
    const int q = tid / 64;           // pair slot 0..5
    const int b = tid & 63;
    const int p = q * 128 + cta;      // global pair id 0..767
    const int l = p >> 8;             // layer
    const int u = p & 255;            // hidden unit

    // Load this CTA's weight slice into SMEM (once per launch)
    for (int idx = tid; idx < 6 * 256; idx += NTHR) {
        int qq = idx >> 8, k = idx & 255;
        int pp = qq * 128 + cta; int ll = pp >> 8, uu = pp & 255;
        const float* W = (ll == 0) ? W0h : ((ll == 1) ? W1h : W2h);
        const float* wp = W + k * 1024 + uu;
        wh4[qq][k] = make_float4(wp[0], wp[256], wp[512], wp[768]);
    }
    for (int idx = tid; idx < 4 * 256; idx += NTHR) {
        int qi = idx >> 8, k = idx & 255;
        int pp = (qi + 2) * 128 + cta; int ll = pp >> 8, uu = pp & 255;
        const float* W = (ll == 1) ? W1x : W2x;
        const float* wp = W + (size_t)(256 + k) * 1024 + uu;
        wx4[qi][k] = make_float4(wp[0], wp[256], wp[512], wp[768]);
    }

    // zero h buffer 0 (each thread owns exactly one slot)
    g_h[0][(((l * 128 + (u >> 1)) * 64 + b) << 1) | (u & 1)] = 0.0f;

    unsigned tgt = *((volatile unsigned*)&g_gen);   // base generation (pre-first-arrive)
    float c = 0.0f;
    float4 gacc = make_float4(0, 0, 0, 0);

    gridbar(++tgt);   // weights + zeroed h visible everywhere

    const int sub = q & 1;
    const int part = q >> 1;
    const int k2s = (part * 128) / 3;
    const int k2e = ((part + 1) * 128) / 3;

    for (int t = 0; t < T_STEPS; t++) {
        const int cur = t & 1, nxt = cur ^ 1;

        // ---- Phase A: gates_l = P[t,l] + h_prev_l @ Wh_l ; finish layer 0 ----
        {
            const float* pp = g_P + ((size_t)(t * 3 + l) * 1024 + u) * 64 + b;
            float p0 = __ldcs(pp);
            float p1 = __ldcs(pp + 16384);
            float p2 = __ldcs(pp + 32768);
            float p3 = __ldcs(pp + 49152);
            const float2* hp = ((const float2*)g_h[cur]) + l * 8192 + b;
            const float4* w = wh4[q];
            float4 a = make_float4(0, 0, 0, 0);
#pragma unroll 8
            for (int k2 = 0; k2 < 128; k2++) {
                float2 hv = hp[k2 * 64];
                float4 w0 = w[2 * k2], w1 = w[2 * k2 + 1];
                a.x += hv.x * w0.x; a.y += hv.x * w0.y; a.z += hv.x * w0.z; a.w += hv.x * w0.w;
                a.x += hv.y * w1.x; a.y += hv.y * w1.y; a.z += hv.y * w1.z; a.w += hv.y * w1.w;
            }
            a.x += p0; a.y += p1; a.z += p2; a.w += p3;
            if (l == 0) {
                float ig = sigf(a.x), jg = tanhf(a.y), fg = sigf(a.z), og = sigf(a.w);
                c = fg * c + ig * jg;
                float h = og * tanhf(c);
                g_h[nxt][((((u >> 1)) * 64 + b) << 1) | (u & 1)] = h;
                if (t == T_STEPS - 1) {
                    out[b * 1536 + u] = c;
                    out[b * 1536 + 256 + u] = h;
                }
            } else {
                gacc = a;
            }
        }
        gridbar(++tgt);

        // ---- Phase B: layer 1 += h0_new @ W1x_bottom (3-way K-split) ----
        {
            const int oq = 2 + sub;
            const float2* hp = ((const float2*)g_h[nxt]) + b;          // layer 0
            const float4* w = wx4[oq - 2];
            float4 a = make_float4(0, 0, 0, 0);
#pragma unroll 4
            for (int k2 = k2s; k2 < k2e; k2++) {
                float2 hv = hp[k2 * 64];
                float4 w0 = w[2 * k2], w1 = w[2 * k2 + 1];
                a.x += hv.x * w0.x; a.y += hv.x * w0.y; a.z += hv.x * w0.z; a.w += hv.x * w0.w;
                a.x += hv.y * w1.x; a.y += hv.y * w1.y; a.z += hv.y * w1.z; a.w += hv.y * w1.w;
            }
            psum[q][b] = a;
            __syncthreads();
            if (q == oq) {
                float4 s0 = psum[sub][b], s1 = psum[2 + sub][b], s2 = psum[4 + sub][b];
                float gx = gacc.x + s0.x + s1.x + s2.x;
                float gy = gacc.y + s0.y + s1.y + s2.y;
                float gz = gacc.z + s0.z + s1.z + s2.z;
                float gw = gacc.w + s0.w + s1.w + s2.w;
                float ig = sigf(gx), jg = tanhf(gy), fg = sigf(gz), og = sigf(gw);
                c = fg * c + ig * jg;
                float h = og * tanhf(c);
                g_h[nxt][(((128 + (u >> 1)) * 64 + b) << 1) | (u & 1)] = h;
                if (t == T_STEPS - 1) {
                    out[b * 1536 + 512 + u] = c;
                    out[b * 1536 + 768 + u] = h;
                }
            }
        }
        gridbar(++tgt);

        // ---- Phase C: layer 2 += h1_new @ W2x_bottom (3-way K-split) ----
        {
            const int oq = 4 + sub;
            const float2* hp = ((const float2*)g_h[nxt]) + 8192 + b;   // layer 1
            const float4* w = wx4[oq - 2];
            float4 a = make_float4(0, 0, 0, 0);
#pragma unroll 4
            for (int k2 = k2s; k2 < k2e; k2++) {
                float2 hv = hp[k2 * 64];
                float4 w0 = w[2 * k2], w1 = w[2 * k2 + 1];
                a.x += hv.x * w0.x; a.y += hv.x * w0.y; a.z += hv.x * w0.z; a.w += hv.x * w0.w;
                a.x += hv.y * w1.x; a.y += hv.y * w1.y; a.z += hv.y * w1.z; a.w += hv.y * w1.w;
            }
            psum[q][b] = a;
            __syncthreads();
            if (q == oq) {
                float4 s0 = psum[sub][b], s1 = psum[2 + sub][b], s2 = psum[4 + sub][b];
                float gx = gacc.x + s0.x + s1.x + s2.x;
                float gy = gacc.y + s0.y + s1.y + s2.y;
                float gz = gacc.z + s0.z + s1.z + s2.z;
                float gw = gacc.w + s0.w + s1.w + s2.w;
                float ig = sigf(gx), jg = tanhf(gy), fg = sigf(gz), og = sigf(gw);
                c = fg * c + ig * jg;
                float h = og * tanhf(c);
                g_h[nxt][(((256 + (u >> 1)) * 64 + b) << 1) | (u & 1)] = h;
                if (t == T_STEPS - 1) {
                    out[b * 1536 + 1024 + u] = c;
                    out[b * 1536 + 1280 + u] = h;
                }
            }
        }
        gridbar(++tgt);
    }
}

// ---------------- launch ----------------
extern "C" void kernel_launch(void* const* d_in, const int* in_sizes, int n_in,
                              void* d_out, int out_size) {
    const int*   ids = (const int*)d_in[0];
    const float* emb = (const float*)d_in[1];
    const float* W0x = (const float*)d_in[2];
    const float* W0h = (const float*)d_in[3];
    const float* b0  = (const float*)d_in[4];
    const float* W1x = (const float*)d_in[5];
    const float* W1h = (const float*)d_in[6];
    const float* b1  = (const float*)d_in[7];
    const float* W2x = (const float*)d_in[8];
    const float* W2h = (const float*)d_in[9];
    const float* b2  = (const float*)d_in[10];
    float* out = (float*)d_out;

    gather_kernel<<<64000, 64>>>(ids, emb);
    dim3 gg(500, 24);
    gemm_kernel<<<gg, 256>>>(W0x, W1x, W2x, b0, b1, b2);
    lstm_kernel<<<NCTA, NTHR>>>(W0h, W1h, W2h, W1x, W2x, out);
}

// round 3
// speedup vs baseline: 1.6552x; 1.6552x over previous
#include <cuda_runtime.h>
#include <cuda_bf16.h>
#include <cstdint>

// Problem constants
#define T_STEPS 1000
#define NCTA 128       // persistent grid
#define NTHR 384       // 6 pairs x 64 batch

// ---------------- device scratch (allocation-free) ----------------
__device__ __nv_bfloat16 g_Xh[(size_t)64000 * 256];   // gathered embeddings, bf16 hi
__device__ __nv_bfloat16 g_Xl[(size_t)64000 * 256];   // bf16 lo residual
__device__ __nv_bfloat16 g_Wh[256 * 3072];            // concat Wx top rows, bf16 hi
__device__ __nv_bfloat16 g_Wl[256 * 3072];            // bf16 lo residual
__device__ float g_P[(size_t)64000 * 3072];           // precomputed x@Wx+b, layout [t][col][b]
__device__ float4 g_h4[2][3 * 64 * 64];               // h ping-pong, [buf][(l*64+k4)*64+b] float4
__device__ unsigned g_cnt;                            // grid barrier count
__device__ unsigned g_gen;                            // grid barrier generation (monotonic)

// ---------------- gather + bf16 split: X[r][k] = emb[ids[b][t]][k] ----------------
__global__ void gather_kernel(const int* __restrict__ ids, const float* __restrict__ emb) {
    int r = blockIdx.x;           // r = t*64 + b
    int t = r >> 6, b = r & 63;
    int id = ids[b * 1000 + t];
    float4 v = ((const float4*)(emb + (size_t)id * 256))[threadIdx.x];
    __nv_bfloat16 hx = __float2bfloat16(v.x), hy = __float2bfloat16(v.y);
    __nv_bfloat16 hz = __float2bfloat16(v.z), hw = __float2bfloat16(v.w);
    __nv_bfloat16 lx = __float2bfloat16(v.x - __bfloat162float(hx));
    __nv_bfloat16 ly = __float2bfloat16(v.y - __bfloat162float(hy));
    __nv_bfloat16 lz = __float2bfloat16(v.z - __bfloat162float(hz));
    __nv_bfloat16 lw = __float2bfloat16(v.w - __bfloat162float(hw));
    size_t o = (size_t)r * 256 + threadIdx.x * 4;
    __nv_bfloat162* dh = (__nv_bfloat162*)(g_Xh + o);
    dh[0] = __nv_bfloat162(hx, hy); dh[1] = __nv_bfloat162(hz, hw);
    __nv_bfloat162* dl = (__nv_bfloat162*)(g_Xl + o);
    dl[0] = __nv_bfloat162(lx, ly); dl[1] = __nv_bfloat162(lz, lw);
}

// ---------------- W split: concat top-256 rows of W0x|W1x|W2x -> bf16 hi/lo ----------------
__global__ void wsplit_kernel(const float* __restrict__ W0x, const float* __restrict__ W1x,
                              const float* __restrict__ W2x) {
    int idx = blockIdx.x * 256 + threadIdx.x;      // over 256*3072
    int k = idx / 3072, c = idx % 3072;
    int l = c >> 10, cc = c & 1023;
    const float* W = (l == 0) ? W0x : ((l == 1) ? W1x : W2x);
    float v = W[(size_t)k * 1024 + cc];
    __nv_bfloat16 h = __float2bfloat16(v);
    g_Wh[idx] = h;
    g_Wl[idx] = __float2bfloat16(v - __bfloat162float(h));
}

// ---------------- bf16-split MMA GEMM: P = X @ W + bias (transposed store) ----------------
__device__ __forceinline__ void mma_bf16(float& d0, float& d1, float& d2, float& d3,
                                         unsigned a0, unsigned a1, unsigned a2, unsigned a3,
                                         unsigned b0, unsigned b1) {
    asm volatile(
        "mma.sync.aligned.m16n8k16.row.col.f32.bf16.bf16.f32 "
        "{%0,%1,%2,%3},{%4,%5,%6,%7},{%8,%9},{%0,%1,%2,%3};"
        : "+f"(d0), "+f"(d1), "+f"(d2), "+f"(d3)
        : "r"(a0), "r"(a1), "r"(a2), "r"(a3), "r"(b0), "r"(b1));
}

#define LDU(arr, elem_idx) (*(const unsigned*)&(arr)[(elem_idx)])

__global__ void __launch_bounds__(256) mma_gemm_kernel(
    const float* __restrict__ b0_, const float* __restrict__ b1_, const float* __restrict__ b2_)
{
    // padded row stride 20 bf16 (40B) for conflict-light fragment loads
    __shared__ __align__(16) __nv_bfloat16 Xh_s[128 * 20];
    __shared__ __align__(16) __nv_bfloat16 Xl_s[128 * 20];
    __shared__ __align__(16) __nv_bfloat16 Wh_s[64 * 20];   // transposed [n][k]
    __shared__ __align__(16) __nv_bfloat16 Wl_s[64 * 20];

    const int tid = threadIdx.x;
    const int warp = tid >> 5, lane = tid & 31;
    const int wm = (warp >> 1) * 32, wn = (warp & 1) * 32;
    const int rbase = blockIdx.x * 128;
    const int cbase = blockIdx.y * 64;
    const int layer = cbase >> 10;
    const float* bias = (layer == 0) ? b0_ : ((layer == 1) ? b1_ : b2_);
    const int r = lane >> 2, tg = lane & 3;

    const int xrow = tid >> 1, xhalf = tid & 1;

    float acc[2][4][4];
#pragma unroll
    for (int i = 0; i < 2; i++)
#pragma unroll
        for (int j = 0; j < 4; j++)
#pragma unroll
            for (int e = 0; e < 4; e++) acc[i][j][e] = 0.0f;

    for (int k0 = 0; k0 < 256; k0 += 16) {
        // global loads (regs) before sync
        uint4 vh = *(const uint4*)(g_Xh + (size_t)(rbase + xrow) * 256 + k0 + xhalf * 8);
        uint4 vl = *(const uint4*)(g_Xl + (size_t)(rbase + xrow) * 256 + k0 + xhalf * 8);
        __nv_bfloat16 wrh[4], wrl[4];
#pragma unroll
        for (int j = 0; j < 4; j++) {
            int i = tid + j * 256;                   // 0..1023
            int kk = i >> 6, cc = i & 63;
            wrh[j] = g_Wh[(size_t)(k0 + kk) * 3072 + cbase + cc];
            wrl[j] = g_Wl[(size_t)(k0 + kk) * 3072 + cbase + cc];
        }
        __syncthreads();
        {
            unsigned* dx = (unsigned*)Xh_s + xrow * 10 + xhalf * 4;
            dx[0] = vh.x; dx[1] = vh.y; dx[2] = vh.z; dx[3] = vh.w;
            unsigned* dl = (unsigned*)Xl_s + xrow * 10 + xhalf * 4;
            dl[0] = vl.x; dl[1] = vl.y; dl[2] = vl.z; dl[3] = vl.w;
        }
#pragma unroll
        for (int j = 0; j < 4; j++) {
            int i = tid + j * 256;
            int kk = i >> 6, cc = i & 63;
            Wh_s[cc * 20 + kk] = wrh[j];
            Wl_s[cc * 20 + kk] = wrl[j];
        }
        __syncthreads();

        // A fragments for both m-tiles (hi and lo)
        unsigned ah[2][4], al[2][4];
#pragma unroll
        for (int mi = 0; mi < 2; mi++) {
            int row0 = (wm + mi * 16 + r) * 20;
            int row1 = row0 + 8 * 20;
            ah[mi][0] = LDU(Xh_s, row0 + 2 * tg);
            ah[mi][1] = LDU(Xh_s, row1 + 2 * tg);
            ah[mi][2] = LDU(Xh_s, row0 + 2 * tg + 8);
            ah[mi][3] = LDU(Xh_s, row1 + 2 * tg + 8);
            al[mi][0] = LDU(Xl_s, row0 + 2 * tg);
            al[mi][1] = LDU(Xl_s, row1 + 2 * tg);
            al[mi][2] = LDU(Xl_s, row0 + 2 * tg + 8);
            al[mi][3] = LDU(Xl_s, row1 + 2 * tg + 8);
        }
#pragma unroll
        for (int ni = 0; ni < 4; ni++) {
            int col = (wn + ni * 8 + r) * 20;
            unsigned bh0 = LDU(Wh_s, col + 2 * tg);
            unsigned bh1 = LDU(Wh_s, col + 2 * tg + 8);
            unsigned bl0 = LDU(Wl_s, col + 2 * tg);
            unsigned bl1 = LDU(Wl_s, col + 2 * tg + 8);
#pragma unroll
            for (int mi = 0; mi < 2; mi++) {
                mma_bf16(acc[mi][ni][0], acc[mi][ni][1], acc[mi][ni][2], acc[mi][ni][3],
                         ah[mi][0], ah[mi][1], ah[mi][2], ah[mi][3], bh0, bh1);
                mma_bf16(acc[mi][ni][0], acc[mi][ni][1], acc[mi][ni][2], acc[mi][ni][3],
                         ah[mi][0], ah[mi][1], ah[mi][2], ah[mi][3], bl0, bl1);
                mma_bf16(acc[mi][ni][0], acc[mi][ni][1], acc[mi][ni][2], acc[mi][ni][3],
                         al[mi][0], al[mi][1], al[mi][2], al[mi][3], bh0, bh1);
            }
        }
    }

    // Epilogue: P[(t*3072 + c)*64 + b] = acc + bias
#pragma unroll
    for (int mi = 0; mi < 2; mi++) {
#pragma unroll
        for (int ni = 0; ni < 4; ni++) {
            int gc = cbase + wn + ni * 8 + 2 * tg;
            float bi0 = bias[gc & 1023];
            float bi1 = bias[(gc + 1) & 1023];
            int grow0 = rbase + wm + mi * 16 + r;
            int grow1 = grow0 + 8;
            size_t o0 = ((size_t)(grow0 >> 6) * 3072 + gc) * 64 + (grow0 & 63);
            size_t o1 = ((size_t)(grow1 >> 6) * 3072 + gc) * 64 + (grow1 & 63);
            g_P[o0]      = acc[mi][ni][0] + bi0;
            g_P[o0 + 64] = acc[mi][ni][1] + bi1;
            g_P[o1]      = acc[mi][ni][2] + bi0;
            g_P[o1 + 64] = acc[mi][ni][3] + bi1;
        }
    }
}

// ---------------- recurrent persistent kernel ----------------
__device__ __forceinline__ float sigf(float x) { return 1.0f / (1.0f + __expf(-x)); }

__device__ __forceinline__ void gridbar(unsigned target) {
    __syncthreads();
    if (threadIdx.x == 0) {
        __threadfence();
        unsigned old = atomicAdd(&g_cnt, 1u);
        if (old == NCTA - 1) {
            g_cnt = 0u;
            __threadfence();
            atomicExch(&g_gen, target);
        } else {
            while (*((volatile unsigned*)&g_gen) != target) { }
        }
        __threadfence();
    }
    __syncthreads();
}

__global__ void __launch_bounds__(NTHR) lstm_kernel(
    const float* __restrict__ W0h, const float* __restrict__ W1h, const float* __restrict__ W2h,
    const float* __restrict__ W1x, const float* __restrict__ W2x,
    float* __restrict__ out)
{
    __shared__ float4 wh4[6][256];    // 24 KB: Wh gate-quads per pair
    __shared__ float4 wx4[4][256];    // 16 KB: Wx bottom-half for l>=1 pairs
    __shared__ float4 psum[6][64];    //  6 KB: K-split partial exchange

    const int tid = threadIdx.x;
    const int cta = blockIdx.x;
    const int q = tid / 64;           // pair slot 0..5
    const int b = tid & 63;
    const int p = q * 128 + cta;      // global pair id 0..767
    const int l = p >> 8;             // layer
    const int u = p & 255;            // hidden unit

    for (int idx = tid; idx < 6 * 256; idx += NTHR) {
        int qq = idx >> 8, k = idx & 255;
        int pp = qq * 128 + cta; int ll = pp >> 8, uu = pp & 255;
        const float* W = (ll == 0) ? W0h : ((ll == 1) ? W1h : W2h);
        const float* wp = W + k * 1024 + uu;
        wh4[qq][k] = make_float4(wp[0], wp[256], wp[512], wp[768]);
    }
    for (int idx = tid; idx < 4 * 256; idx += NTHR) {
        int qi = idx >> 8, k = idx & 255;
        int pp = (qi + 2) * 128 + cta; int ll = pp >> 8, uu = pp & 255;
        const float* W = (ll == 1) ? W1x : W2x;
        const float* wp = W + (size_t)(256 + k) * 1024 + uu;
        wx4[qi][k] = make_float4(wp[0], wp[256], wp[512], wp[768]);
    }

    // zero h buffer 0 (each thread owns exactly one scalar slot)
    ((float*)&g_h4[0][(l * 64 + (u >> 2)) * 64 + b])[u & 3] = 0.0f;

    unsigned tgt = *((volatile unsigned*)&g_gen);
    float c = 0.0f;
    float4 gacc = make_float4(0, 0, 0, 0);

    gridbar(++tgt);   // weights + zeroed h visible everywhere

    const int sub = q & 1;
    const int part = q >> 1;
    const int k4s = (part * 64) / 3;
    const int k4e = ((part + 1) * 64) / 3;

    for (int t = 0; t < T_STEPS; t++) {
        const int cur = t & 1, nxt = cur ^ 1;

        // ---- Phase A: gates_l = P[t,l] + h_prev_l @ Wh_l ; finish layer 0 ----
        {
            const float* pp = g_P + ((size_t)(t * 3 + l) * 1024 + u) * 64 + b;
            float p0 = __ldcs(pp);
            float p1 = __ldcs(pp + 16384);
            float p2 = __ldcs(pp + 32768);
            float p3 = __ldcs(pp + 49152);
            const float4* hp = g_h4[cur] + l * 4096 + b;
            const float4* w = wh4[q];
            float4 a = make_float4(0, 0, 0, 0);
#pragma unroll 8
            for (int k4 = 0; k4 < 64; k4++) {
                float4 hv = __ldcg(hp + k4 * 64);
                float4 w0 = w[4 * k4], w1 = w[4 * k4 + 1], w2 = w[4 * k4 + 2], w3 = w[4 * k4 + 3];
                a.x += hv.x * w0.x; a.y += hv.x * w0.y; a.z += hv.x * w0.z; a.w += hv.x * w0.w;
                a.x += hv.y * w1.x; a.y += hv.y * w1.y; a.z += hv.y * w1.z; a.w += hv.y * w1.w;
                a.x += hv.z * w2.x; a.y += hv.z * w2.y; a.z += hv.z * w2.z; a.w += hv.z * w2.w;
                a.x += hv.w * w3.x; a.y += hv.w * w3.y; a.z += hv.w * w3.z; a.w += hv.w * w3.w;
            }
            a.x += p0; a.y += p1; a.z += p2; a.w += p3;
            if (l == 0) {
                float ig = sigf(a.x), jg = tanhf(a.y), fg = sigf(a.z), og = sigf(a.w);
                c = fg * c + ig * jg;
                float h = og * tanhf(c);
                ((float*)&g_h4[nxt][(u >> 2) * 64 + b])[u & 3] = h;
                if (t == T_STEPS - 1) {
                    out[b * 1536 + u] = c;
                    out[b * 1536 + 256 + u] = h;
                }
            } else {
                gacc = a;
            }
        }
        gridbar(++tgt);

        // ---- Phase B: layer 1 += h0_new @ W1x_bottom (3-way K-split) ----
        {
            const int oq = 2 + sub;
            const float4* hp = g_h4[nxt] + b;               // layer 0
            const float4* w = wx4[oq - 2];
            float4 a = make_float4(0, 0, 0, 0);
#pragma unroll 4
            for (int k4 = k4s; k4 < k4e; k4++) {
                float4 hv = __ldcg(hp + k4 * 64);
                float4 w0 = w[4 * k4], w1 = w[4 * k4 + 1], w2 = w[4 * k4 + 2], w3 = w[4 * k4 + 3];
                a.x += hv.x * w0.x; a.y += hv.x * w0.y; a.z += hv.x * w0.z; a.w += hv.x * w0.w;
                a.x += hv.y * w1.x; a.y += hv.y * w1.y; a.z += hv.y * w1.z; a.w += hv.y * w1.w;
                a.x += hv.z * w2.x; a.y += hv.z * w2.y; a.z += hv.z * w2.z; a.w += hv.z * w2.w;
                a.x += hv.w * w3.x; a.y += hv.w * w3.y; a.z += hv.w * w3.z; a.w += hv.w * w3.w;
            }
            psum[q][b] = a;
            __syncthreads();
            if (q == oq) {
                float4 s0 = psum[sub][b], s1 = psum[2 + sub][b], s2 = psum[4 + sub][b];
                float gx = gacc.x + s0.x + s1.x + s2.x;
                float gy = gacc.y + s0.y + s1.y + s2.y;
                float gz = gacc.z + s0.z + s1.z + s2.z;
                float gw = gacc.w + s0.w + s1.w + s2.w;
                float ig = sigf(gx), jg = tanhf(gy), fg = sigf(gz), og = sigf(gw);
                c = fg * c + ig * jg;
                float h = og * tanhf(c);
                ((float*)&g_h4[nxt][(64 + (u >> 2)) * 64 + b])[u & 3] = h;
                if (t == T_STEPS - 1) {
                    out[b * 1536 + 512 + u] = c;
                    out[b * 1536 + 768 + u] = h;
                }
            }
        }
        gridbar(++tgt);

        // ---- Phase C: layer 2 += h1_new @ W2x_bottom (3-way K-split) ----
        {
            const int oq = 4 + sub;
            const float4* hp = g_h4[nxt] + 4096 + b;        // layer 1
            const float4* w = wx4[oq - 2];
            float4 a = make_float4(0, 0, 0, 0);
#pragma unroll 4
            for (int k4 = k4s; k4 < k4e; k4++) {
                float4 hv = __ldcg(hp + k4 * 64);
                float4 w0 = w[4 * k4], w1 = w[4 * k4 + 1], w2 = w[4 * k4 + 2], w3 = w[4 * k4 + 3];
                a.x += hv.x * w0.x; a.y += hv.x * w0.y; a.z += hv.x * w0.z; a.w += hv.x * w0.w;
                a.x += hv.y * w1.x; a.y += hv.y * w1.y; a.z += hv.y * w1.z; a.w += hv.y * w1.w;
                a.x += hv.z * w2.x; a.y += hv.z * w2.y; a.z += hv.z * w2.z; a.w += hv.z * w2.w;
                a.x += hv.w * w3.x; a.y += hv.w * w3.y; a.z += hv.w * w3.z; a.w += hv.w * w3.w;
            }
            psum[q][b] = a;
            __syncthreads();
            if (q == oq) {
                float4 s0 = psum[sub][b], s1 = psum[2 + sub][b], s2 = psum[4 + sub][b];
                float gx = gacc.x + s0.x + s1.x + s2.x;
                float gy = gacc.y + s0.y + s1.y + s2.y;
                float gz = gacc.z + s0.z + s1.z + s2.z;
                float gw = gacc.w + s0.w + s1.w + s2.w;
                float ig = sigf(gx), jg = tanhf(gy), fg = sigf(gz), og = sigf(gw);
                c = fg * c + ig * jg;
                float h = og * tanhf(c);
                ((float*)&g_h4[nxt][(128 + (u >> 2)) * 64 + b])[u & 3] = h;
                if (t == T_STEPS - 1) {
                    out[b * 1536 + 1024 + u] = c;
                    out[b * 1536 + 1280 + u] = h;
                }
            }
        }
        gridbar(++tgt);
    }
}

// ---------------- launch ----------------
extern "C" void kernel_launch(void* const* d_in, const int* in_sizes, int n_in,
                              void* d_out, int out_size) {
    const int*   ids = (const int*)d_in[0];
    const float* emb = (const float*)d_in[1];
    const float* W0x = (const float*)d_in[2];
    const float* W0h = (const float*)d_in[3];
    const float* b0  = (const float*)d_in[4];
    const float* W1x = (const float*)d_in[5];
    const float* W1h = (const float*)d_in[6];
    const float* b1  = (const float*)d_in[7];
    const float* W2x = (const float*)d_in[8];
    const float* W2h = (const float*)d_in[9];
    const float* b2  = (const float*)d_in[10];
    float* out = (float*)d_out;

    gather_kernel<<<64000, 64>>>(ids, emb);
    wsplit_kernel<<<3072, 256>>>(W0x, W1x, W2x);
    dim3 gg(500, 48);
    mma_gemm_kernel<<<gg, 256>>>(b0, b1, b2);
    lstm_kernel<<<NCTA, NTHR>>>(W0h, W1h, W2h, W1x, W2x, out);
}

// round 4
// speedup vs baseline: 1.9264x; 1.1639x over previous
#include <cuda_runtime.h>
#include <cuda_bf16.h>
#include <cstdint>

// Problem constants
#define T_STEPS 1000
#define NCTA 128       // persistent grid
#define NTHR 384       // 6 pairs x 64 batch

// ---------------- device scratch (allocation-free) ----------------
__device__ __nv_bfloat16 g_Xh[(size_t)64000 * 256];   // gathered embeddings, bf16 hi
__device__ __nv_bfloat16 g_Xl[(size_t)64000 * 256];   // bf16 lo residual
__device__ __nv_bfloat16 g_Wh[256 * 3072];            // concat Wx top rows, bf16 hi
__device__ __nv_bfloat16 g_Wl[256 * 3072];            // bf16 lo residual
__device__ float g_P[(size_t)64000 * 3072];           // precomputed x@Wx+b, layout [t][col][b]
__device__ float4 g_h4[2][3 * 64 * 64];               // h ping-pong, [buf][(l*64+k4)*64+b] float4
__device__ unsigned g_cnt;                            // grid barrier count
__device__ unsigned g_gen;                            // grid barrier generation (monotonic)

// ---------------- gather + bf16 split: X[r][k] = emb[ids[b][t]][k] ----------------
__global__ void gather_kernel(const int* __restrict__ ids, const float* __restrict__ emb) {
    int r = blockIdx.x;           // r = t*64 + b
    int t = r >> 6, b = r & 63;
    int id = ids[b * 1000 + t];
    float4 v = ((const float4*)(emb + (size_t)id * 256))[threadIdx.x];
    __nv_bfloat16 hx = __float2bfloat16(v.x), hy = __float2bfloat16(v.y);
    __nv_bfloat16 hz = __float2bfloat16(v.z), hw = __float2bfloat16(v.w);
    __nv_bfloat16 lx = __float2bfloat16(v.x - __bfloat162float(hx));
    __nv_bfloat16 ly = __float2bfloat16(v.y - __bfloat162float(hy));
    __nv_bfloat16 lz = __float2bfloat16(v.z - __bfloat162float(hz));
    __nv_bfloat16 lw = __float2bfloat16(v.w - __bfloat162float(hw));
    size_t o = (size_t)r * 256 + threadIdx.x * 4;
    __nv_bfloat162* dh = (__nv_bfloat162*)(g_Xh + o);
    dh[0] = __nv_bfloat162(hx, hy); dh[1] = __nv_bfloat162(hz, hw);
    __nv_bfloat162* dl = (__nv_bfloat162*)(g_Xl + o);
    dl[0] = __nv_bfloat162(lx, ly); dl[1] = __nv_bfloat162(lz, lw);
}

// ---------------- W split: concat top-256 rows of W0x|W1x|W2x -> bf16 hi/lo ----------------
__global__ void wsplit_kernel(const float* __restrict__ W0x, const float* __restrict__ W1x,
                              const float* __restrict__ W2x) {
    int idx = blockIdx.x * 256 + threadIdx.x;      // over 256*3072
    int k = idx / 3072, c = idx % 3072;
    int l = c >> 10, cc = c & 1023;
    const float* W = (l == 0) ? W0x : ((l == 1) ? W1x : W2x);
    float v = W[(size_t)k * 1024 + cc];
    __nv_bfloat16 h = __float2bfloat16(v);
    g_Wh[idx] = h;
    g_Wl[idx] = __float2bfloat16(v - __bfloat162float(h));
}

// ---------------- bf16-split MMA GEMM: P = X @ W + bias (transposed store) ----------------
__device__ __forceinline__ void mma_bf16(float& d0, float& d1, float& d2, float& d3,
                                         unsigned a0, unsigned a1, unsigned a2, unsigned a3,
                                         unsigned b0, unsigned b1) {
    asm volatile(
        "mma.sync.aligned.m16n8k16.row.col.f32.bf16.bf16.f32 "
        "{%0,%1,%2,%3},{%4,%5,%6,%7},{%8,%9},{%0,%1,%2,%3};"
        : "+f"(d0), "+f"(d1), "+f"(d2), "+f"(d3)
        : "r"(a0), "r"(a1), "r"(a2), "r"(a3), "r"(b0), "r"(b1));
}

#define LDU(arr, elem_idx) (*(const unsigned*)&(arr)[(elem_idx)])

__global__ void __launch_bounds__(256) mma_gemm_kernel(
    const float* __restrict__ b0_, const float* __restrict__ b1_, const float* __restrict__ b2_)
{
    __shared__ __align__(16) __nv_bfloat16 Xh_s[128 * 20];
    __shared__ __align__(16) __nv_bfloat16 Xl_s[128 * 20];
    __shared__ __align__(16) __nv_bfloat16 Wh_s[64 * 20];   // transposed [n][k]
    __shared__ __align__(16) __nv_bfloat16 Wl_s[64 * 20];

    const int tid = threadIdx.x;
    const int warp = tid >> 5, lane = tid & 31;
    const int wm = (warp >> 1) * 32, wn = (warp & 1) * 32;
    const int rbase = blockIdx.x * 128;
    const int cbase = blockIdx.y * 64;
    const int layer = cbase >> 10;
    const float* bias = (layer == 0) ? b0_ : ((layer == 1) ? b1_ : b2_);
    const int r = lane >> 2, tg = lane & 3;

    const int xrow = tid >> 1, xhalf = tid & 1;

    float acc[2][4][4];
#pragma unroll
    for (int i = 0; i < 2; i++)
#pragma unroll
        for (int j = 0; j < 4; j++)
#pragma unroll
            for (int e = 0; e < 4; e++) acc[i][j][e] = 0.0f;

    for (int k0 = 0; k0 < 256; k0 += 16) {
        uint4 vh = *(const uint4*)(g_Xh + (size_t)(rbase + xrow) * 256 + k0 + xhalf * 8);
        uint4 vl = *(const uint4*)(g_Xl + (size_t)(rbase + xrow) * 256 + k0 + xhalf * 8);
        __nv_bfloat16 wrh[4], wrl[4];
#pragma unroll
        for (int j = 0; j < 4; j++) {
            int i = tid + j * 256;
            int kk = i >> 6, cc = i & 63;
            wrh[j] = g_Wh[(size_t)(k0 + kk) * 3072 + cbase + cc];
            wrl[j] = g_Wl[(size_t)(k0 + kk) * 3072 + cbase + cc];
        }
        __syncthreads();
        {
            unsigned* dx = (unsigned*)Xh_s + xrow * 10 + xhalf * 4;
            dx[0] = vh.x; dx[1] = vh.y; dx[2] = vh.z; dx[3] = vh.w;
            unsigned* dl = (unsigned*)Xl_s + xrow * 10 + xhalf * 4;
            dl[0] = vl.x; dl[1] = vl.y; dl[2] = vl.z; dl[3] = vl.w;
        }
#pragma unroll
        for (int j = 0; j < 4; j++) {
            int i = tid + j * 256;
            int kk = i >> 6, cc = i & 63;
            Wh_s[cc * 20 + kk] = wrh[j];
            Wl_s[cc * 20 + kk] = wrl[j];
        }
        __syncthreads();

        unsigned ah[2][4], al[2][4];
#pragma unroll
        for (int mi = 0; mi < 2; mi++) {
            int row0 = (wm + mi * 16 + r) * 20;
            int row1 = row0 + 8 * 20;
            ah[mi][0] = LDU(Xh_s, row0 + 2 * tg);
            ah[mi][1] = LDU(Xh_s, row1 + 2 * tg);
            ah[mi][2] = LDU(Xh_s, row0 + 2 * tg + 8);
            ah[mi][3] = LDU(Xh_s, row1 + 2 * tg + 8);
            al[mi][0] = LDU(Xl_s, row0 + 2 * tg);
            al[mi][1] = LDU(Xl_s, row1 + 2 * tg);
            al[mi][2] = LDU(Xl_s, row0 + 2 * tg + 8);
            al[mi][3] = LDU(Xl_s, row1 + 2 * tg + 8);
        }
#pragma unroll
        for (int ni = 0; ni < 4; ni++) {
            int col = (wn + ni * 8 + r) * 20;
            unsigned bh0 = LDU(Wh_s, col + 2 * tg);
            unsigned bh1 = LDU(Wh_s, col + 2 * tg + 8);
            unsigned bl0 = LDU(Wl_s, col + 2 * tg);
            unsigned bl1 = LDU(Wl_s, col + 2 * tg + 8);
#pragma unroll
            for (int mi = 0; mi < 2; mi++) {
                mma_bf16(acc[mi][ni][0], acc[mi][ni][1], acc[mi][ni][2], acc[mi][ni][3],
                         ah[mi][0], ah[mi][1], ah[mi][2], ah[mi][3], bh0, bh1);
                mma_bf16(acc[mi][ni][0], acc[mi][ni][1], acc[mi][ni][2], acc[mi][ni][3],
                         ah[mi][0], ah[mi][1], ah[mi][2], ah[mi][3], bl0, bl1);
                mma_bf16(acc[mi][ni][0], acc[mi][ni][1], acc[mi][ni][2], acc[mi][ni][3],
                         al[mi][0], al[mi][1], al[mi][2], al[mi][3], bh0, bh1);
            }
        }
    }

#pragma unroll
    for (int mi = 0; mi < 2; mi++) {
#pragma unroll
        for (int ni = 0; ni < 4; ni++) {
            int gc = cbase + wn + ni * 8 + 2 * tg;
            float bi0 = bias[gc & 1023];
            float bi1 = bias[(gc + 1) & 1023];
            int grow0 = rbase + wm + mi * 16 + r;
            int grow1 = grow0 + 8;
            size_t o0 = ((size_t)(grow0 >> 6) * 3072 + gc) * 64 + (grow0 & 63);
            size_t o1 = ((size_t)(grow1 >> 6) * 3072 + gc) * 64 + (grow1 & 63);
            g_P[o0]      = acc[mi][ni][0] + bi0;
            g_P[o0 + 64] = acc[mi][ni][1] + bi1;
            g_P[o1]      = acc[mi][ni][2] + bi0;
            g_P[o1 + 64] = acc[mi][ni][3] + bi1;
        }
    }
}

// ---------------- recurrent persistent kernel (skewed wavefront) ----------------
__device__ __forceinline__ float sigf(float x) { return 1.0f / (1.0f + __expf(-x)); }

__device__ __forceinline__ void gridbar(unsigned target) {
    __syncthreads();
    if (threadIdx.x == 0) {
        __threadfence();
        unsigned old = atomicAdd(&g_cnt, 1u);
        if (old == NCTA - 1) {
            g_cnt = 0u;
            __threadfence();
            atomicExch(&g_gen, target);
        } else {
            while (*((volatile unsigned*)&g_gen) != target) { }
        }
        __threadfence();
    }
    __syncthreads();
}

__global__ void __launch_bounds__(NTHR) lstm_kernel(
    const float* __restrict__ W0h, const float* __restrict__ W1h, const float* __restrict__ W2h,
    const float* __restrict__ W1x, const float* __restrict__ W2x,
    float* __restrict__ out)
{
    __shared__ float4 wh4[6][256];    // 24 KB: Wh gate-quads per pair
    __shared__ float4 wx4[4][256];    // 16 KB: Wx bottom-half for l>=1 pairs

    const int tid = threadIdx.x;
    const int cta = blockIdx.x;
    const int q = tid / 64;           // pair slot 0..5
    const int b = tid & 63;
    const int p = q * 128 + cta;      // global pair id 0..767
    const int l = p >> 8;             // layer (q<2 -> 0, q<4 -> 1, else 2)
    const int u = p & 255;            // hidden unit

    // Load this CTA's weight slice into SMEM (once per launch)
    for (int idx = tid; idx < 6 * 256; idx += NTHR) {
        int qq = idx >> 8, k = idx & 255;
        int pp = qq * 128 + cta; int ll = pp >> 8, uu = pp & 255;
        const float* W = (ll == 0) ? W0h : ((ll == 1) ? W1h : W2h);
        const float* wp = W + k * 1024 + uu;
        wh4[qq][k] = make_float4(wp[0], wp[256], wp[512], wp[768]);
    }
    for (int idx = tid; idx < 4 * 256; idx += NTHR) {
        int qi = idx >> 8, k = idx & 255;
        int pp = (qi + 2) * 128 + cta; int ll = pp >> 8, uu = pp & 255;
        const float* W = (ll == 1) ? W1x : W2x;
        const float* wp = W + (size_t)(256 + k) * 1024 + uu;
        wx4[qi][k] = make_float4(wp[0], wp[256], wp[512], wp[768]);
    }

    // zero BOTH h buffers (wavefront start: layers read zeros from either parity)
    ((float*)&g_h4[0][(l * 64 + (u >> 2)) * 64 + b])[u & 3] = 0.0f;
    ((float*)&g_h4[1][(l * 64 + (u >> 2)) * 64 + b])[u & 3] = 0.0f;

    unsigned tgt = *((volatile unsigned*)&g_gen);
    float c = 0.0f;

    gridbar(++tgt);   // weights + zeroed h visible everywhere

    const int hw_slot = (l * 64 + (u >> 2)) * 64 + b;   // write slot (float4 index)
    const int hw_lane = u & 3;

    // Super-steps: layer l processes t = s - l. One barrier per super-step.
    for (int s = 0; s < T_STEPS + 2; s++) {
        const int t = s - l;
        const int wbuf = s & 1, rbuf = wbuf ^ 1;

        if (t >= 0 && t < T_STEPS) {
            const float* pp = g_P + ((size_t)(t * 3 + l) * 1024 + u) * 64 + b;
            float p0 = __ldcs(pp);
            float p1 = __ldcs(pp + 16384);
            float p2 = __ldcs(pp + 32768);
            float p3 = __ldcs(pp + 49152);

            // recurrent part: h_l(t-1) @ Wh_l
            const float4* hrec = g_h4[rbuf] + l * 4096 + b;
            const float4* w = wh4[q];
            float4 a = make_float4(0, 0, 0, 0);
#pragma unroll 8
            for (int k4 = 0; k4 < 64; k4++) {
                float4 hv = __ldcg(hrec + k4 * 64);
                float4 w0 = w[4 * k4], w1 = w[4 * k4 + 1], w2 = w[4 * k4 + 2], w3 = w[4 * k4 + 3];
                a.x += hv.x * w0.x; a.y += hv.x * w0.y; a.z += hv.x * w0.z; a.w += hv.x * w0.w;
                a.x += hv.y * w1.x; a.y += hv.y * w1.y; a.z += hv.y * w1.z; a.w += hv.y * w1.w;
                a.x += hv.z * w2.x; a.y += hv.z * w2.y; a.z += hv.z * w2.z; a.w += hv.z * w2.w;
                a.x += hv.w * w3.x; a.y += hv.w * w3.y; a.z += hv.w * w3.z; a.w += hv.w * w3.w;
            }

            // input part for layers 1,2: h_{l-1}(t) @ Wx_bottom (published last super-step)
            if (q >= 2) {
                const float4* hin = g_h4[rbuf] + (l - 1) * 4096 + b;
                const float4* wx = wx4[q - 2];
#pragma unroll 8
                for (int k4 = 0; k4 < 64; k4++) {
                    float4 hv = __ldcg(hin + k4 * 64);
                    float4 w0 = wx[4 * k4], w1 = wx[4 * k4 + 1], w2 = wx[4 * k4 + 2], w3 = wx[4 * k4 + 3];
                    a.x += hv.x * w0.x; a.y += hv.x * w0.y; a.z += hv.x * w0.z; a.w += hv.x * w0.w;
                    a.x += hv.y * w1.x; a.y += hv.y * w1.y; a.z += hv.y * w1.z; a.w += hv.y * w1.w;
                    a.x += hv.z * w2.x; a.y += hv.z * w2.y; a.z += hv.z * w2.z; a.w += hv.z * w2.w;
                    a.x += hv.w * w3.x; a.y += hv.w * w3.y; a.z += hv.w * w3.z; a.w += hv.w * w3.w;
                }
            }

            a.x += p0; a.y += p1; a.z += p2; a.w += p3;
            float ig = sigf(a.x), jg = tanhf(a.y), fg = sigf(a.z), og = sigf(a.w);
            c = fg * c + ig * jg;
            float h = og * tanhf(c);
            ((float*)&g_h4[wbuf][hw_slot])[hw_lane] = h;
            if (t == T_STEPS - 1) {
                out[b * 1536 + l * 512 + u] = c;
                out[b * 1536 + l * 512 + 256 + u] = h;
            }
        }
        gridbar(++tgt);
    }
}

// ---------------- launch ----------------
extern "C" void kernel_launch(void* const* d_in, const int* in_sizes, int n_in,
                              void* d_out, int out_size) {
    const int*   ids = (const int*)d_in[0];
    const float* emb = (const float*)d_in[1];
    const float* W0x = (const float*)d_in[2];
    const float* W0h = (const float*)d_in[3];
    const float* b0  = (const float*)d_in[4];
    const float* W1x = (const float*)d_in[5];
    const float* W1h = (const float*)d_in[6];
    const float* b1  = (const float*)d_in[7];
    const float* W2x = (const float*)d_in[8];
    const float* W2h = (const float*)d_in[9];
    const float* b2  = (const float*)d_in[10];
    float* out = (float*)d_out;

    gather_kernel<<<64000, 64>>>(ids, emb);
    wsplit_kernel<<<3072, 256>>>(W0x, W1x, W2x);
    dim3 gg(500, 48);
    mma_gemm_kernel<<<gg, 256>>>(b0, b1, b2);
    lstm_kernel<<<NCTA, NTHR>>>(W0h, W1h, W2h, W1x, W2x, out);
}

// round 5
// speedup vs baseline: 3.0571x; 1.5870x over previous
#include <cuda_runtime.h>
#include <cuda_bf16.h>
#include <cstdint>

// Problem constants
#define T_STEPS 1000
#define NCTA_L 96      // persistent grid for LSTM (96 = 3 layers x 32 col-blocks)
#define NTHR_L 128     // 4 warps

// ---------------- device scratch (allocation-free) ----------------
__device__ __nv_bfloat16 g_Xh[(size_t)64000 * 256];   // gathered embeddings, bf16 hi
__device__ __nv_bfloat16 g_Xl[(size_t)64000 * 256];   // bf16 lo residual
__device__ __nv_bfloat16 g_Wh[256 * 3072];            // concat Wx top rows, bf16 hi
__device__ __nv_bfloat16 g_Wl[256 * 3072];            // bf16 lo residual
__device__ float g_P[(size_t)64000 * 3072];           // precomputed x@Wx+b, layout [t][col][b]
__device__ uint2 g_B[NCTA_L * 8192];                  // pre-packed recurrent B fragments (6.3MB)
__device__ __nv_bfloat16 g_hb[2 * 2 * 3 * 64 * 256];  // h [buf][split][l][b][k] bf16
__device__ unsigned g_cnt;                            // grid barrier count
__device__ unsigned g_gen;                            // grid barrier generation (monotonic)

// ---------------- gather + bf16 split: X[r][k] = emb[ids[b][t]][k] ----------------
__global__ void gather_kernel(const int* __restrict__ ids, const float* __restrict__ emb) {
    int r = blockIdx.x;           // r = t*64 + b
    int t = r >> 6, b = r & 63;
    int id = ids[b * 1000 + t];
    float4 v = ((const float4*)(emb + (size_t)id * 256))[threadIdx.x];
    __nv_bfloat16 hx = __float2bfloat16(v.x), hy = __float2bfloat16(v.y);
    __nv_bfloat16 hz = __float2bfloat16(v.z), hw = __float2bfloat16(v.w);
    __nv_bfloat16 lx = __float2bfloat16(v.x - __bfloat162float(hx));
    __nv_bfloat16 ly = __float2bfloat16(v.y - __bfloat162float(hy));
    __nv_bfloat16 lz = __float2bfloat16(v.z - __bfloat162float(hz));
    __nv_bfloat16 lw = __float2bfloat16(v.w - __bfloat162float(hw));
    size_t o = (size_t)r * 256 + threadIdx.x * 4;
    __nv_bfloat162* dh = (__nv_bfloat162*)(g_Xh + o);
    dh[0] = __nv_bfloat162(hx, hy); dh[1] = __nv_bfloat162(hz, hw);
    __nv_bfloat162* dl = (__nv_bfloat162*)(g_Xl + o);
    dl[0] = __nv_bfloat162(lx, ly); dl[1] = __nv_bfloat162(lz, lw);
}

// ---------------- W split: concat top-256 rows of W0x|W1x|W2x -> bf16 hi/lo ----------------
__global__ void wsplit_kernel(const float* __restrict__ W0x, const float* __restrict__ W1x,
                              const float* __restrict__ W2x) {
    int idx = blockIdx.x * 256 + threadIdx.x;      // over 256*3072
    int k = idx / 3072, c = idx % 3072;
    int l = c >> 10, cc = c & 1023;
    const float* W = (l == 0) ? W0x : ((l == 1) ? W1x : W2x);
    float v = W[(size_t)k * 1024 + cc];
    __nv_bfloat16 h = __float2bfloat16(v);
    g_Wh[idx] = h;
    g_Wl[idx] = __float2bfloat16(v - __bfloat162float(h));
}

// ---------------- pre-pack recurrent weights into m16n8k16 B fragments ----------------
// g_B[cta][chunk(5b)][split(1b)][ni(2b)][lane(5b)] = uint2{b0,b1}
//   b0 = W[k0+2tg .. +1][oc] packed bf16x2 ; b1 = W[k0+2tg+8 .. +9][oc]
//   n = lane>>2, c = ni*8+n, unit = cb*8 + (c>>2), gate = c&3, oc = gate*256+unit
//   k<256 -> Wh_l[k][oc];  k in [256,512) -> Wx_l[k][oc] (bottom half rows)
__global__ void bprep_kernel(
    const float* __restrict__ W0h, const float* __restrict__ W1h, const float* __restrict__ W2h,
    const float* __restrict__ W1x, const float* __restrict__ W2x)
{
    int gidx = blockIdx.x * 256 + threadIdx.x;     // over 96*8192
    int cta = gidx >> 13, rem = gidx & 8191;
    int chunk = rem >> 8, split = (rem >> 7) & 1, ni = (rem >> 5) & 3, lane = rem & 31;
    int l = cta / 32, cb = cta % 32;
    int n = lane >> 2, tg = lane & 3;
    int c = ni * 8 + n;
    int oc = (c & 3) * 256 + cb * 8 + (c >> 2);
    int k0 = chunk * 16;

    uint2 out_v = make_uint2(0u, 0u);
    if (!(l == 0 && chunk >= 16)) {
        const float* Whl = (l == 0) ? W0h : ((l == 1) ? W1h : W2h);
        const float* Wxl = (l <= 1) ? W1x : W2x;   // unused for l==0
        int offs[4] = {2 * tg, 2 * tg + 1, 2 * tg + 8, 2 * tg + 9};
        unsigned short sv[4];
#pragma unroll
        for (int j = 0; j < 4; j++) {
            int k = k0 + offs[j];
            float v = (k < 256) ? Whl[(size_t)k * 1024 + oc] : Wxl[(size_t)k * 1024 + oc];
            __nv_bfloat16 h = __float2bfloat16(v);
            __nv_bfloat16 lo = __float2bfloat16(v - __bfloat162float(h));
            __nv_bfloat16 sel = split ? lo : h;
            sv[j] = __bfloat16_as_ushort(sel);
        }
        out_v.x = (unsigned)sv[0] | ((unsigned)sv[1] << 16);
        out_v.y = (unsigned)sv[2] | ((unsigned)sv[3] << 16);
    }
    g_B[gidx] = out_v;
}

// ---------------- MMA primitive ----------------
__device__ __forceinline__ void mma_bf16(float& d0, float& d1, float& d2, float& d3,
                                         unsigned a0, unsigned a1, unsigned a2, unsigned a3,
                                         unsigned b0, unsigned b1) {
    asm volatile(
        "mma.sync.aligned.m16n8k16.row.col.f32.bf16.bf16.f32 "
        "{%0,%1,%2,%3},{%4,%5,%6,%7},{%8,%9},{%0,%1,%2,%3};"
        : "+f"(d0), "+f"(d1), "+f"(d2), "+f"(d3)
        : "r"(a0), "r"(a1), "r"(a2), "r"(a3), "r"(b0), "r"(b1));
}

#define LDU(arr, elem_idx) (*(const unsigned*)&(arr)[(elem_idx)])

// ---------------- bf16-split MMA GEMM: P = X @ W + bias (transposed store) ----------------
__global__ void __launch_bounds__(256) mma_gemm_kernel(
    const float* __restrict__ b0_, const float* __restrict__ b1_, const float* __restrict__ b2_)
{
    __shared__ __align__(16) __nv_bfloat16 Xh_s[128 * 20];
    __shared__ __align__(16) __nv_bfloat16 Xl_s[128 * 20];
    __shared__ __align__(16) __nv_bfloat16 Wh_s[64 * 20];   // transposed [n][k]
    __shared__ __align__(16) __nv_bfloat16 Wl_s[64 * 20];

    const int tid = threadIdx.x;
    const int warp = tid >> 5, lane = tid & 31;
    const int wm = (warp >> 1) * 32, wn = (warp & 1) * 32;
    const int rbase = blockIdx.x * 128;
    const int cbase = blockIdx.y * 64;
    const int layer = cbase >> 10;
    const float* bias = (layer == 0) ? b0_ : ((layer == 1) ? b1_ : b2_);
    const int r = lane >> 2, tg = lane & 3;
    const int xrow = tid >> 1, xhalf = tid & 1;

    float acc[2][4][4];
#pragma unroll
    for (int i = 0; i < 2; i++)
#pragma unroll
        for (int j = 0; j < 4; j++)
#pragma unroll
            for (int e = 0; e < 4; e++) acc[i][j][e] = 0.0f;

    for (int k0 = 0; k0 < 256; k0 += 16) {
        uint4 vh = *(const uint4*)(g_Xh + (size_t)(rbase + xrow) * 256 + k0 + xhalf * 8);
        uint4 vl = *(const uint4*)(g_Xl + (size_t)(rbase + xrow) * 256 + k0 + xhalf * 8);
        __nv_bfloat16 wrh[4], wrl[4];
#pragma unroll
        for (int j = 0; j < 4; j++) {
            int i = tid + j * 256;
            int kk = i >> 6, cc = i & 63;
            wrh[j] = g_Wh[(size_t)(k0 + kk) * 3072 + cbase + cc];
            wrl[j] = g_Wl[(size_t)(k0 + kk) * 3072 + cbase + cc];
        }
        __syncthreads();
        {
            unsigned* dx = (unsigned*)Xh_s + xrow * 10 + xhalf * 4;
            dx[0] = vh.x; dx[1] = vh.y; dx[2] = vh.z; dx[3] = vh.w;
            unsigned* dl = (unsigned*)Xl_s + xrow * 10 + xhalf * 4;
            dl[0] = vl.x; dl[1] = vl.y; dl[2] = vl.z; dl[3] = vl.w;
        }
#pragma unroll
        for (int j = 0; j < 4; j++) {
            int i = tid + j * 256;
            int kk = i >> 6, cc = i & 63;
            Wh_s[cc * 20 + kk] = wrh[j];
            Wl_s[cc * 20 + kk] = wrl[j];
        }
        __syncthreads();

        unsigned ah[2][4], al[2][4];
#pragma unroll
        for (int mi = 0; mi < 2; mi++) {
            int row0 = (wm + mi * 16 + r) * 20;
            int row1 = row0 + 8 * 20;
            ah[mi][0] = LDU(Xh_s, row0 + 2 * tg);
            ah[mi][1] = LDU(Xh_s, row1 + 2 * tg);
            ah[mi][2] = LDU(Xh_s, row0 + 2 * tg + 8);
            ah[mi][3] = LDU(Xh_s, row1 + 2 * tg + 8);
            al[mi][0] = LDU(Xl_s, row0 + 2 * tg);
            al[mi][1] = LDU(Xl_s, row1 + 2 * tg);
            al[mi][2] = LDU(Xl_s, row0 + 2 * tg + 8);
            al[mi][3] = LDU(Xl_s, row1 + 2 * tg + 8);
        }
#pragma unroll
        for (int ni = 0; ni < 4; ni++) {
            int col = (wn + ni * 8 + r) * 20;
            unsigned bh0 = LDU(Wh_s, col + 2 * tg);
            unsigned bh1 = LDU(Wh_s, col + 2 * tg + 8);
            unsigned bl0 = LDU(Wl_s, col + 2 * tg);
            unsigned bl1 = LDU(Wl_s, col + 2 * tg + 8);
#pragma unroll
            for (int mi = 0; mi < 2; mi++) {
                mma_bf16(acc[mi][ni][0], acc[mi][ni][1], acc[mi][ni][2], acc[mi][ni][3],
                         ah[mi][0], ah[mi][1], ah[mi][2], ah[mi][3], bh0, bh1);
                mma_bf16(acc[mi][ni][0], acc[mi][ni][1], acc[mi][ni][2], acc[mi][ni][3],
                         ah[mi][0], ah[mi][1], ah[mi][2], ah[mi][3], bl0, bl1);
                mma_bf16(acc[mi][ni][0], acc[mi][ni][1], acc[mi][ni][2], acc[mi][ni][3],
                         al[mi][0], al[mi][1], al[mi][2], al[mi][3], bh0, bh1);
            }
        }
    }

#pragma unroll
    for (int mi = 0; mi < 2; mi++) {
#pragma unroll
        for (int ni = 0; ni < 4; ni++) {
            int gc = cbase + wn + ni * 8 + 2 * tg;
            float bi0 = bias[gc & 1023];
            float bi1 = bias[(gc + 1) & 1023];
            int grow0 = rbase + wm + mi * 16 + r;
            int grow1 = grow0 + 8;
            size_t o0 = ((size_t)(grow0 >> 6) * 3072 + gc) * 64 + (grow0 & 63);
            size_t o1 = ((size_t)(grow1 >> 6) * 3072 + gc) * 64 + (grow1 & 63);
            g_P[o0]      = acc[mi][ni][0] + bi0;
            g_P[o0 + 64] = acc[mi][ni][1] + bi1;
            g_P[o1]      = acc[mi][ni][2] + bi0;
            g_P[o1 + 64] = acc[mi][ni][3] + bi1;
        }
    }
}

// ---------------- recurrent persistent kernel (wavefront + tensor-core) ----------------
__device__ __forceinline__ float sigf(float x) { return 1.0f / (1.0f + __expf(-x)); }

__device__ __forceinline__ unsigned ldcg_u32(const void* p) {
    unsigned v;
    asm volatile("ld.global.cg.b32 %0, [%1];" : "=r"(v) : "l"(p));
    return v;
}

__device__ __forceinline__ void gridbar(unsigned target) {
    __syncthreads();
    if (threadIdx.x == 0) {
        __threadfence();
        unsigned old = atomicAdd(&g_cnt, 1u);
        if (old == NCTA_L - 1) {
            g_cnt = 0u;
            __threadfence();
            atomicExch(&g_gen, target);
        } else {
            while (*((volatile unsigned*)&g_gen) != target) { }
        }
        __threadfence();
    }
    __syncthreads();
}

__global__ void __launch_bounds__(NTHR_L) lstm_kernel(float* __restrict__ out)
{
    extern __shared__ uint2 Bs[];     // 64 KB: [chunk][split][ni][lane]

    const int tid = threadIdx.x;
    const int cta = blockIdx.x;
    const int w = tid >> 5, lane = tid & 31;
    const int r = lane >> 2, tg = lane & 3;
    const int l = cta / 32, cb = cta % 32;
    const int br  = w * 16 + r;       // batch row (even-tg output)
    const int br8 = br + 8;           // batch row (odd-tg output)

    // load pre-packed B fragments into SMEM (once)
    {
        const uint4* src = (const uint4*)g_B + (size_t)cta * 4096;
        uint4* dst = (uint4*)Bs;
        for (int i = tid; i < 4096; i += NTHR_L) dst[i] = src[i];
    }

    // zero h buffers (both parities, both splits)
    {
        unsigned* hz = (unsigned*)g_hb;   // 98304 u32
        for (int i = cta * NTHR_L + tid; i < 98304; i += NCTA_L * NTHR_L) hz[i] = 0u;
    }

    unsigned tgt = *((volatile unsigned*)&g_gen);
    float cst[4] = {0.0f, 0.0f, 0.0f, 0.0f};

    gridbar(++tgt);   // SMEM (local) + zeroed h visible everywhere

    const int nchunks = (l == 0) ? 16 : 32;
    // h plane base offsets (elements)
    const int PL = 64 * 256;          // per-(buf,split,layer) plane
    const int row_off = 0;            // computed per access

    for (int s = 0; s < T_STEPS + 2; s++) {
        const int t = s - l;
        const int wbuf = s & 1, rbuf = wbuf ^ 1;

        if (t >= 0 && t < T_STEPS) {
            // ---- prefetch P (streaming) ----
            const float* basep = g_P + (size_t)(t * 3 + l) * 1024 * 64;
            float pv[4][4];
#pragma unroll
            for (int ni = 0; ni < 4; ni++) {
                int ug = cb * 8 + 2 * ni + (tg >> 1);
                int oc0 = (tg & 1) * 512 + ug;        // gate (tg&1)*2
                int oc1 = oc0 + 256;                   // gate +1
                pv[ni][0] = __ldcs(basep + (size_t)oc0 * 64 + br);
                pv[ni][1] = __ldcs(basep + (size_t)oc1 * 64 + br);
                pv[ni][2] = __ldcs(basep + (size_t)oc0 * 64 + br8);
                pv[ni][3] = __ldcs(basep + (size_t)oc1 * 64 + br8);
            }

            // ---- MMA mainloop ----
            const __nv_bfloat16* ownhi = g_hb + ((rbuf * 2 + 0) * 3 + l) * PL;
            const __nv_bfloat16* ownlo = g_hb + ((rbuf * 2 + 1) * 3 + l) * PL;
            const __nv_bfloat16* belhi = (l > 0) ? g_hb + ((rbuf * 2 + 0) * 3 + (l - 1)) * PL : ownhi;
            const __nv_bfloat16* bello = (l > 0) ? g_hb + ((rbuf * 2 + 1) * 3 + (l - 1)) * PL : ownlo;

            float acc[4][4];
#pragma unroll
            for (int ni = 0; ni < 4; ni++)
#pragma unroll
                for (int e = 0; e < 4; e++) acc[ni][e] = 0.0f;

            for (int chunk = 0; chunk < nchunks; chunk++) {
                const __nv_bfloat16* shi = (chunk < 16) ? ownhi : belhi;
                const __nv_bfloat16* slo = (chunk < 16) ? ownlo : bello;
                const int kb = (chunk & 15) * 16;
                unsigned ah0 = ldcg_u32(shi + br  * 256 + kb + 2 * tg);
                unsigned ah1 = ldcg_u32(shi + br8 * 256 + kb + 2 * tg);
                unsigned ah2 = ldcg_u32(shi + br  * 256 + kb + 2 * tg + 8);
                unsigned ah3 = ldcg_u32(shi + br8 * 256 + kb + 2 * tg + 8);
                unsigned al0 = ldcg_u32(slo + br  * 256 + kb + 2 * tg);
                unsigned al1 = ldcg_u32(slo + br8 * 256 + kb + 2 * tg);
                unsigned al2 = ldcg_u32(slo + br  * 256 + kb + 2 * tg + 8);
                unsigned al3 = ldcg_u32(slo + br8 * 256 + kb + 2 * tg + 8);
                const uint2* bsc = Bs + (chunk * 2) * 128;
#pragma unroll
                for (int ni = 0; ni < 4; ni++) {
                    uint2 bh = bsc[ni * 32 + lane];
                    uint2 bl = bsc[128 + ni * 32 + lane];
                    mma_bf16(acc[ni][0], acc[ni][1], acc[ni][2], acc[ni][3],
                             ah0, ah1, ah2, ah3, bh.x, bh.y);
                    mma_bf16(acc[ni][0], acc[ni][1], acc[ni][2], acc[ni][3],
                             ah0, ah1, ah2, ah3, bl.x, bl.y);
                    mma_bf16(acc[ni][0], acc[ni][1], acc[ni][2], acc[ni][3],
                             al0, al1, al2, al3, bh.x, bh.y);
                }
            }

            // ---- epilogue: gate exchange + LSTM cell + h publish ----
            __nv_bfloat16* whi = g_hb + ((wbuf * 2 + 0) * 3 + l) * PL;
            __nv_bfloat16* wlo = g_hb + ((wbuf * 2 + 1) * 3 + l) * PL;
#pragma unroll
            for (int ni = 0; ni < 4; ni++) {
                float v0 = acc[ni][0] + pv[ni][0];
                float v1 = acc[ni][1] + pv[ni][1];
                float v2 = acc[ni][2] + pv[ni][2];
                float v3 = acc[ni][3] + pv[ni][3];
                float s0 = __shfl_xor_sync(0xffffffffu, (tg & 1) ? v0 : v2, 1);
                float s1 = __shfl_xor_sync(0xffffffffu, (tg & 1) ? v1 : v3, 1);
                float gi_, gj_, gf_, go_;
                int brow;
                if (!(tg & 1)) { gi_ = v0; gj_ = v1; gf_ = s0; go_ = s1; brow = br; }
                else           { gi_ = s0; gj_ = s1; gf_ = v2; go_ = v3; brow = br8; }
                float cn = sigf(gf_) * cst[ni] + sigf(gi_) * tanhf(gj_);
                cst[ni] = cn;
                float h = sigf(go_) * tanhf(cn);
                __nv_bfloat16 hh = __float2bfloat16(h);
                __nv_bfloat16 hl = __float2bfloat16(h - __bfloat162float(hh));
                int ug = cb * 8 + 2 * ni + (tg >> 1);
                whi[brow * 256 + ug] = hh;
                wlo[brow * 256 + ug] = hl;
                if (t == T_STEPS - 1) {
                    out[brow * 1536 + l * 512 + ug] = cn;
                    out[brow * 1536 + l * 512 + 256 + ug] = h;
                }
            }
        }
        gridbar(++tgt);
    }
}

// ---------------- launch ----------------
extern "C" void kernel_launch(void* const* d_in, const int* in_sizes, int n_in,
                              void* d_out, int out_size) {
    const int*   ids = (const int*)d_in[0];
    const float* emb = (const float*)d_in[1];
    const float* W0x = (const float*)d_in[2];
    const float* W0h = (const float*)d_in[3];
    const float* b0  = (const float*)d_in[4];
    const float* W1x = (const float*)d_in[5];
    const float* W1h = (const float*)d_in[6];
    const float* b1  = (const float*)d_in[7];
    const float* W2x = (const float*)d_in[8];
    const float* W2h = (const float*)d_in[9];
    const float* b2  = (const float*)d_in[10];
    float* out = (float*)d_out;

    static bool attr_set = false;
    if (!attr_set) {
        cudaFuncSetAttribute(lstm_kernel, cudaFuncAttributeMaxDynamicSharedMemorySize, 65536);
        attr_set = true;
    }

    gather_kernel<<<64000, 64>>>(ids, emb);
    wsplit_kernel<<<3072, 256>>>(W0x, W1x, W2x);
    bprep_kernel<<<3072, 256>>>(W0h, W1h, W2h, W1x, W2x);
    dim3 gg(500, 48);
    mma_gemm_kernel<<<gg, 256>>>(b0, b1, b2);
    lstm_kernel<<<NCTA_L, NTHR_L, 65536>>>(out);
}

// round 6
// speedup vs baseline: 3.2297x; 1.0564x over previous
#include <cuda_runtime.h>
#include <cuda_bf16.h>
#include <cstdint>

// Problem constants
#define T_STEPS 1000
#define NCTA_L 96      // persistent grid for LSTM (96 = 3 layers x 32 col-blocks)
#define NTHR_L 256     // 8 warps: 2 K-split groups x 4 batch warps

// ---------------- device scratch (allocation-free) ----------------
__device__ __nv_bfloat16 g_Xh[(size_t)64000 * 256];   // gathered embeddings, bf16 hi
__device__ __nv_bfloat16 g_Xl[(size_t)64000 * 256];   // bf16 lo residual
__device__ __nv_bfloat16 g_Wh[256 * 3072];            // concat Wx top rows, bf16 hi
__device__ __nv_bfloat16 g_Wl[256 * 3072];            // bf16 lo residual
__device__ float g_P[(size_t)64000 * 3072];           // precomputed x@Wx+b, layout [t][col][b]
__device__ uint2 g_B[NCTA_L * 8192];                  // pre-packed recurrent B fragments (6.3MB)
__device__ __nv_bfloat16 g_hb[2 * 2 * 3 * 64 * 256];  // h [buf][split][l][b][k] bf16
__device__ unsigned g_cnt;                            // grid barrier count
__device__ unsigned g_gen;                            // grid barrier generation (monotonic)

// ---------------- gather + bf16 split: X[r][k] = emb[ids[b][t]][k] ----------------
__global__ void gather_kernel(const int* __restrict__ ids, const float* __restrict__ emb) {
    int r = blockIdx.x;           // r = t*64 + b
    int t = r >> 6, b = r & 63;
    int id = ids[b * 1000 + t];
    float4 v = ((const float4*)(emb + (size_t)id * 256))[threadIdx.x];
    __nv_bfloat16 hx = __float2bfloat16(v.x), hy = __float2bfloat16(v.y);
    __nv_bfloat16 hz = __float2bfloat16(v.z), hw = __float2bfloat16(v.w);
    __nv_bfloat16 lx = __float2bfloat16(v.x - __bfloat162float(hx));
    __nv_bfloat16 ly = __float2bfloat16(v.y - __bfloat162float(hy));
    __nv_bfloat16 lz = __float2bfloat16(v.z - __bfloat162float(hz));
    __nv_bfloat16 lw = __float2bfloat16(v.w - __bfloat162float(hw));
    size_t o = (size_t)r * 256 + threadIdx.x * 4;
    __nv_bfloat162* dh = (__nv_bfloat162*)(g_Xh + o);
    dh[0] = __nv_bfloat162(hx, hy); dh[1] = __nv_bfloat162(hz, hw);
    __nv_bfloat162* dl = (__nv_bfloat162*)(g_Xl + o);
    dl[0] = __nv_bfloat162(lx, ly); dl[1] = __nv_bfloat162(lz, lw);
}

// ---------------- W split: concat top-256 rows of W0x|W1x|W2x -> bf16 hi/lo ----------------
__global__ void wsplit_kernel(const float* __restrict__ W0x, const float* __restrict__ W1x,
                              const float* __restrict__ W2x) {
    int idx = blockIdx.x * 256 + threadIdx.x;      // over 256*3072
    int k = idx / 3072, c = idx % 3072;
    int l = c >> 10, cc = c & 1023;
    const float* W = (l == 0) ? W0x : ((l == 1) ? W1x : W2x);
    float v = W[(size_t)k * 1024 + cc];
    __nv_bfloat16 h = __float2bfloat16(v);
    g_Wh[idx] = h;
    g_Wl[idx] = __float2bfloat16(v - __bfloat162float(h));
}

// ---------------- pre-pack recurrent weights into m16n8k16 B fragments ----------------
__global__ void bprep_kernel(
    const float* __restrict__ W0h, const float* __restrict__ W1h, const float* __restrict__ W2h,
    const float* __restrict__ W1x, const float* __restrict__ W2x)
{
    int gidx = blockIdx.x * 256 + threadIdx.x;     // over 96*8192
    int cta = gidx >> 13, rem = gidx & 8191;
    int chunk = rem >> 8, split = (rem >> 7) & 1, ni = (rem >> 5) & 3, lane = rem & 31;
    int l = cta / 32, cb = cta % 32;
    int n = lane >> 2, tg = lane & 3;
    int c = ni * 8 + n;
    int oc = (c & 3) * 256 + cb * 8 + (c >> 2);
    int k0 = chunk * 16;

    uint2 out_v = make_uint2(0u, 0u);
    if (!(l == 0 && chunk >= 16)) {
        const float* Whl = (l == 0) ? W0h : ((l == 1) ? W1h : W2h);
        const float* Wxl = (l <= 1) ? W1x : W2x;   // unused for l==0
        int offs[4] = {2 * tg, 2 * tg + 1, 2 * tg + 8, 2 * tg + 9};
        unsigned short sv[4];
#pragma unroll
        for (int j = 0; j < 4; j++) {
            int k = k0 + offs[j];
            float v = (k < 256) ? Whl[(size_t)k * 1024 + oc] : Wxl[(size_t)k * 1024 + oc];
            __nv_bfloat16 h = __float2bfloat16(v);
            __nv_bfloat16 lo = __float2bfloat16(v - __bfloat162float(h));
            __nv_bfloat16 sel = split ? lo : h;
            sv[j] = __bfloat16_as_ushort(sel);
        }
        out_v.x = (unsigned)sv[0] | ((unsigned)sv[1] << 16);
        out_v.y = (unsigned)sv[2] | ((unsigned)sv[3] << 16);
    }
    g_B[gidx] = out_v;
}

// ---------------- MMA primitive ----------------
__device__ __forceinline__ void mma_bf16(float& d0, float& d1, float& d2, float& d3,
                                         unsigned a0, unsigned a1, unsigned a2, unsigned a3,
                                         unsigned b0, unsigned b1) {
    asm volatile(
        "mma.sync.aligned.m16n8k16.row.col.f32.bf16.bf16.f32 "
        "{%0,%1,%2,%3},{%4,%5,%6,%7},{%8,%9},{%0,%1,%2,%3};"
        : "+f"(d0), "+f"(d1), "+f"(d2), "+f"(d3)
        : "r"(a0), "r"(a1), "r"(a2), "r"(a3), "r"(b0), "r"(b1));
}

#define LDU(arr, elem_idx) (*(const unsigned*)&(arr)[(elem_idx)])

// ---------------- bf16-split MMA GEMM: P = X @ W + bias (transposed store) ----------------
__global__ void __launch_bounds__(256) mma_gemm_kernel(
    const float* __restrict__ b0_, const float* __restrict__ b1_, const float* __restrict__ b2_)
{
    __shared__ __align__(16) __nv_bfloat16 Xh_s[128 * 20];
    __shared__ __align__(16) __nv_bfloat16 Xl_s[128 * 20];
    __shared__ __align__(16) __nv_bfloat16 Wh_s[64 * 20];   // transposed [n][k]
    __shared__ __align__(16) __nv_bfloat16 Wl_s[64 * 20];

    const int tid = threadIdx.x;
    const int warp = tid >> 5, lane = tid & 31;
    const int wm = (warp >> 1) * 32, wn = (warp & 1) * 32;
    const int rbase = blockIdx.x * 128;
    const int cbase = blockIdx.y * 64;
    const int layer = cbase >> 10;
    const float* bias = (layer == 0) ? b0_ : ((layer == 1) ? b1_ : b2_);
    const int r = lane >> 2, tg = lane & 3;
    const int xrow = tid >> 1, xhalf = tid & 1;

    float acc[2][4][4];
#pragma unroll
    for (int i = 0; i < 2; i++)
#pragma unroll
        for (int j = 0; j < 4; j++)
#pragma unroll
            for (int e = 0; e < 4; e++) acc[i][j][e] = 0.0f;

    for (int k0 = 0; k0 < 256; k0 += 16) {
        uint4 vh = *(const uint4*)(g_Xh + (size_t)(rbase + xrow) * 256 + k0 + xhalf * 8);
        uint4 vl = *(const uint4*)(g_Xl + (size_t)(rbase + xrow) * 256 + k0 + xhalf * 8);
        __nv_bfloat16 wrh[4], wrl[4];
#pragma unroll
        for (int j = 0; j < 4; j++) {
            int i = tid + j * 256;
            int kk = i >> 6, cc = i & 63;
            wrh[j] = g_Wh[(size_t)(k0 + kk) * 3072 + cbase + cc];
            wrl[j] = g_Wl[(size_t)(k0 + kk) * 3072 + cbase + cc];
        }
        __syncthreads();
        {
            unsigned* dx = (unsigned*)Xh_s + xrow * 10 + xhalf * 4;
            dx[0] = vh.x; dx[1] = vh.y; dx[2] = vh.z; dx[3] = vh.w;
            unsigned* dl = (unsigned*)Xl_s + xrow * 10 + xhalf * 4;
            dl[0] = vl.x; dl[1] = vl.y; dl[2] = vl.z; dl[3] = vl.w;
        }
#pragma unroll
        for (int j = 0; j < 4; j++) {
            int i = tid + j * 256;
            int kk = i >> 6, cc = i & 63;
            Wh_s[cc * 20 + kk] = wrh[j];
            Wl_s[cc * 20 + kk] = wrl[j];
        }
        __syncthreads();

        unsigned ah[2][4], al[2][4];
#pragma unroll
        for (int mi = 0; mi < 2; mi++) {
            int row0 = (wm + mi * 16 + r) * 20;
            int row1 = row0 + 8 * 20;
            ah[mi][0] = LDU(Xh_s, row0 + 2 * tg);
            ah[mi][1] = LDU(Xh_s, row1 + 2 * tg);
            ah[mi][2] = LDU(Xh_s, row0 + 2 * tg + 8);
            ah[mi][3] = LDU(Xh_s, row1 + 2 * tg + 8);
            al[mi][0] = LDU(Xl_s, row0 + 2 * tg);
            al[mi][1] = LDU(Xl_s, row1 + 2 * tg);
            al[mi][2] = LDU(Xl_s, row0 + 2 * tg + 8);
            al[mi][3] = LDU(Xl_s, row1 + 2 * tg + 8);
        }
#pragma unroll
        for (int ni = 0; ni < 4; ni++) {
            int col = (wn + ni * 8 + r) * 20;
            unsigned bh0 = LDU(Wh_s, col + 2 * tg);
            unsigned bh1 = LDU(Wh_s, col + 2 * tg + 8);
            unsigned bl0 = LDU(Wl_s, col + 2 * tg);
            unsigned bl1 = LDU(Wl_s, col + 2 * tg + 8);
#pragma unroll
            for (int mi = 0; mi < 2; mi++) {
                mma_bf16(acc[mi][ni][0], acc[mi][ni][1], acc[mi][ni][2], acc[mi][ni][3],
                         ah[mi][0], ah[mi][1], ah[mi][2], ah[mi][3], bh0, bh1);
                mma_bf16(acc[mi][ni][0], acc[mi][ni][1], acc[mi][ni][2], acc[mi][ni][3],
                         ah[mi][0], ah[mi][1], ah[mi][2], ah[mi][3], bl0, bl1);
                mma_bf16(acc[mi][ni][0], acc[mi][ni][1], acc[mi][ni][2], acc[mi][ni][3],
                         al[mi][0], al[mi][1], al[mi][2], al[mi][3], bh0, bh1);
            }
        }
    }

#pragma unroll
    for (int mi = 0; mi < 2; mi++) {
#pragma unroll
        for (int ni = 0; ni < 4; ni++) {
            int gc = cbase + wn + ni * 8 + 2 * tg;
            float bi0 = bias[gc & 1023];
            float bi1 = bias[(gc + 1) & 1023];
            int grow0 = rbase + wm + mi * 16 + r;
            int grow1 = grow0 + 8;
            size_t o0 = ((size_t)(grow0 >> 6) * 3072 + gc) * 64 + (grow0 & 63);
            size_t o1 = ((size_t)(grow1 >> 6) * 3072 + gc) * 64 + (grow1 & 63);
            g_P[o0]      = acc[mi][ni][0] + bi0;
            g_P[o0 + 64] = acc[mi][ni][1] + bi1;
            g_P[o1]      = acc[mi][ni][2] + bi0;
            g_P[o1 + 64] = acc[mi][ni][3] + bi1;
        }
    }
}

// ---------------- recurrent persistent kernel (wavefront + TC + K-split + pipelining) ----------------
__device__ __forceinline__ float sigf(float x) { return 1.0f / (1.0f + __expf(-x)); }

__device__ __forceinline__ unsigned ldcg_u32(const void* p) {
    unsigned v;
    asm volatile("ld.global.cg.b32 %0, [%1];" : "=r"(v) : "l"(p));
    return v;
}

__device__ __forceinline__ void gridbar(unsigned target) {
    __syncthreads();
    if (threadIdx.x == 0) {
        __threadfence();
        unsigned old = atomicAdd(&g_cnt, 1u);
        if (old == NCTA_L - 1) {
            g_cnt = 0u;
            __threadfence();
            atomicExch(&g_gen, target);
        } else {
            while (*((volatile unsigned*)&g_gen) != target) { }
        }
        __threadfence();
    }
    __syncthreads();
}

__global__ void __launch_bounds__(NTHR_L) lstm_kernel(float* __restrict__ out)
{
    extern __shared__ uint2 Bs[];             // 64 KB: [chunk][split][ni][lane]
    __shared__ float red[4][32][16];          // 8 KB: K-split partial exchange

    const int tid = threadIdx.x;
    const int cta = blockIdx.x;
    const int w = tid >> 5, lane = tid & 31;
    const int wq = w & 3, grp = w >> 2;       // batch-warp index, K-split group
    const int r = lane >> 2, tg = lane & 3;
    const int l = cta / 32, cb = cta % 32;
    const int br  = wq * 16 + r;              // batch row (even-tg output)
    const int br8 = br + 8;

    // load pre-packed B fragments into SMEM (once)
    {
        const uint4* src = (const uint4*)g_B + (size_t)cta * 4096;
        uint4* dst = (uint4*)Bs;
        for (int i = tid; i < 4096; i += NTHR_L) dst[i] = src[i];
    }
    // zero h buffers (both parities, both splits)
    {
        unsigned* hz = (unsigned*)g_hb;   // 98304 u32
        for (int i = cta * NTHR_L + tid; i < 98304; i += NCTA_L * NTHR_L) hz[i] = 0u;
    }

    unsigned tgt = *((volatile unsigned*)&g_gen);
    float cst[4] = {0.0f, 0.0f, 0.0f, 0.0f};

    gridbar(++tgt);   // SMEM (local) + zeroed h visible everywhere

    const int half = (l == 0) ? 8 : 16;
    const int cstart = grp * half;            // global chunk range [cstart, cstart+half)
    const int PL = 64 * 256;                  // per-(buf,split,layer) h plane (elements)

    for (int s = 0; s < T_STEPS + 2; s++) {
        const int t = s - l;
        const int wbuf = s & 1, rbuf = wbuf ^ 1;

        if (t >= 0 && t < T_STEPS) {
            // ---- prefetch P (group 0 only; streaming) ----
            float pv[4][4];
            if (grp == 0) {
                const float* basep = g_P + (size_t)(t * 3 + l) * 1024 * 64;
#pragma unroll
                for (int ni = 0; ni < 4; ni++) {
                    int ug = cb * 8 + 2 * ni + (tg >> 1);
                    int oc0 = (tg & 1) * 512 + ug;
                    int oc1 = oc0 + 256;
                    pv[ni][0] = __ldcs(basep + (size_t)oc0 * 64 + br);
                    pv[ni][1] = __ldcs(basep + (size_t)oc1 * 64 + br);
                    pv[ni][2] = __ldcs(basep + (size_t)oc0 * 64 + br8);
                    pv[ni][3] = __ldcs(basep + (size_t)oc1 * 64 + br8);
                }
            }

            // ---- select h source planes for this group's chunk range ----
            const int srcl = (l > 0 && grp == 1) ? (l - 1) : l;
            const __nv_bfloat16* shi = g_hb + ((rbuf * 2 + 0) * 3 + srcl) * PL;
            const __nv_bfloat16* slo = g_hb + ((rbuf * 2 + 1) * 3 + srcl) * PL;

            float acc[4][4];
#pragma unroll
            for (int ni = 0; ni < 4; ni++)
#pragma unroll
                for (int e = 0; e < 4; e++) acc[ni][e] = 0.0f;

            // ---- MMA mainloop with register double-buffering ----
            unsigned a[8], an[8];
            {
                const int kb = (cstart & 15) * 16;
                a[0] = ldcg_u32(shi + br  * 256 + kb + 2 * tg);
                a[1] = ldcg_u32(shi + br8 * 256 + kb + 2 * tg);
                a[2] = ldcg_u32(shi + br  * 256 + kb + 2 * tg + 8);
                a[3] = ldcg_u32(shi + br8 * 256 + kb + 2 * tg + 8);
                a[4] = ldcg_u32(slo + br  * 256 + kb + 2 * tg);
                a[5] = ldcg_u32(slo + br8 * 256 + kb + 2 * tg);
                a[6] = ldcg_u32(slo + br  * 256 + kb + 2 * tg + 8);
                a[7] = ldcg_u32(slo + br8 * 256 + kb + 2 * tg + 8);
            }
#pragma unroll 2
            for (int j = 0; j < half; j++) {
                const int gc = cstart + j;
                if (j + 1 < half) {
                    const int kb = ((gc + 1) & 15) * 16;
                    an[0] = ldcg_u32(shi + br  * 256 + kb + 2 * tg);
                    an[1] = ldcg_u32(shi + br8 * 256 + kb + 2 * tg);
                    an[2] = ldcg_u32(shi + br  * 256 + kb + 2 * tg + 8);
                    an[3] = ldcg_u32(shi + br8 * 256 + kb + 2 * tg + 8);
                    an[4] = ldcg_u32(slo + br  * 256 + kb + 2 * tg);
                    an[5] = ldcg_u32(slo + br8 * 256 + kb + 2 * tg);
                    an[6] = ldcg_u32(slo + br  * 256 + kb + 2 * tg + 8);
                    an[7] = ldcg_u32(slo + br8 * 256 + kb + 2 * tg + 8);
                }
                const uint2* bsc = Bs + gc * 256;
#pragma unroll
                for (int ni = 0; ni < 4; ni++) {
                    uint2 bh = bsc[ni * 32 + lane];
                    uint2 bl = bsc[128 + ni * 32 + lane];
                    mma_bf16(acc[ni][0], acc[ni][1], acc[ni][2], acc[ni][3],
                             a[0], a[1], a[2], a[3], bh.x, bh.y);
                    mma_bf16(acc[ni][0], acc[ni][1], acc[ni][2], acc[ni][3],
                             a[0], a[1], a[2], a[3], bl.x, bl.y);
                    mma_bf16(acc[ni][0], acc[ni][1], acc[ni][2], acc[ni][3],
                             a[4], a[5], a[6], a[7], bh.x, bh.y);
                }
                if (j + 1 < half) {
#pragma unroll
                    for (int e = 0; e < 8; e++) a[e] = an[e];
                }
            }

            // ---- K-split reduction: group 1 -> SMEM, group 0 adds ----
            if (grp == 1) {
#pragma unroll
                for (int ni = 0; ni < 4; ni++) {
                    red[wq][lane][ni * 4 + 0] = acc[ni][0];
                    red[wq][lane][ni * 4 + 1] = acc[ni][1];
                    red[wq][lane][ni * 4 + 2] = acc[ni][2];
                    red[wq][lane][ni * 4 + 3] = acc[ni][3];
                }
            }
            __syncthreads();

            if (grp == 0) {
                // ---- epilogue: add partner partial + P, gate exchange, cell, publish ----
                __nv_bfloat16* whi = g_hb + ((wbuf * 2 + 0) * 3 + l) * PL;
                __nv_bfloat16* wlo = g_hb + ((wbuf * 2 + 1) * 3 + l) * PL;
#pragma unroll
                for (int ni = 0; ni < 4; ni++) {
                    float v0 = acc[ni][0] + red[wq][lane][ni * 4 + 0] + pv[ni][0];
                    float v1 = acc[ni][1] + red[wq][lane][ni * 4 + 1] + pv[ni][1];
                    float v2 = acc[ni][2] + red[wq][lane][ni * 4 + 2] + pv[ni][2];
                    float v3 = acc[ni][3] + red[wq][lane][ni * 4 + 3] + pv[ni][3];
                    float s0 = __shfl_xor_sync(0xffffffffu, (tg & 1) ? v0 : v2, 1);
                    float s1 = __shfl_xor_sync(0xffffffffu, (tg & 1) ? v1 : v3, 1);
                    float gi_, gj_, gf_, go_;
                    int brow;
                    if (!(tg & 1)) { gi_ = v0; gj_ = v1; gf_ = s0; go_ = s1; brow = br; }
                    else           { gi_ = s0; gj_ = s1; gf_ = v2; go_ = v3; brow = br8; }
                    float cn = sigf(gf_) * cst[ni] + sigf(gi_) * tanhf(gj_);
                    cst[ni] = cn;
                    float h = sigf(go_) * tanhf(cn);
                    __nv_bfloat16 hh = __float2bfloat16(h);
                    __nv_bfloat16 hl = __float2bfloat16(h - __bfloat162float(hh));
                    int ug = cb * 8 + 2 * ni + (tg >> 1);
                    whi[brow * 256 + ug] = hh;
                    wlo[brow * 256 + ug] = hl;
                    if (t == T_STEPS - 1) {
                        out[brow * 1536 + l * 512 + ug] = cn;
                        out[brow * 1536 + l * 512 + 256 + ug] = h;
                    }
                }
            }
        }
        gridbar(++tgt);
    }
}

// ---------------- launch ----------------
extern "C" void kernel_launch(void* const* d_in, const int* in_sizes, int n_in,
                              void* d_out, int out_size) {
    const int*   ids = (const int*)d_in[0];
    const float* emb = (const float*)d_in[1];
    const float* W0x = (const float*)d_in[2];
    const float* W0h = (const float*)d_in[3];
    const float* b0  = (const float*)d_in[4];
    const float* W1x = (const float*)d_in[5];
    const float* W1h = (const float*)d_in[6];
    const float* b1  = (const float*)d_in[7];
    const float* W2x = (const float*)d_in[8];
    const float* W2h = (const float*)d_in[9];
    const float* b2  = (const float*)d_in[10];
    float* out = (float*)d_out;

    static bool attr_set = false;
    if (!attr_set) {
        cudaFuncSetAttribute(lstm_kernel, cudaFuncAttributeMaxDynamicSharedMemorySize, 65536);
        attr_set = true;
    }

    gather_kernel<<<64000, 64>>>(ids, emb);
    wsplit_kernel<<<3072, 256>>>(W0x, W1x, W2x);
    bprep_kernel<<<3072, 256>>>(W0h, W1h, W2h, W1x, W2x);
    dim3 gg(500, 48);
    mma_gemm_kernel<<<gg, 256>>>(b0, b1, b2);
    lstm_kernel<<<NCTA_L, NTHR_L, 65536>>>(out);
}